// round 14
// baseline (speedup 1.0000x reference)
#include <cuda_runtime.h>
#include <cuda_fp16.h>
#include <math.h>

#define UU 100000
#define II 50000
#define DD 64
#define EE 2000000
#define NN 150000   // UU + II
#define NB 147      // ceil(NN / 1024) scan blocks
#define FIXS 1048576.0f              // 2^20 fixed-point scale for degree
#define MASK44 ((1ULL << 44) - 1ULL)
#define ITEM_BLOCKS 6250             // II / 8
#define USER_BLOCKS 12500            // UU / 8
#define EMBED_BLOCKS (ITEM_BLOCKS + USER_BLOCKS)

// ---- device scratch (static; no allocation anywhere) ----
__device__ __half2 g_x0[NN * 32];    // layer outputs, fp16: row = 32 half2 = 128 B
__device__ __half2 g_x1[NN * 32];
__device__ __half2 g_x2[NN * 32];
__device__ int2    g_edge[2 * EE + 3 * NN + 8];  // padded (mult of 4) CSR payload
__device__ unsigned long long g_pack[NN];        // (cnt << 44) | deg_fixedpoint
__device__ unsigned long long g_desc[NB];        // lookback: (state<<32)|value
__device__ float g_dinv[NN];
__device__ int   g_off [NN + 1];
__device__ int   g_pos [NN];

// ---------------------------------------------------------------------------
// fused L0 embeddings + scratch zeroing.
// blocks [0, ITEM_BLOCKS): item path; [ITEM_BLOCKS, EMBED_BLOCKS): user path.
__global__ void k_embed(const float* __restrict__ uw,
                        const float* __restrict__ audio,
                        const float* __restrict__ artw,
                        const float* __restrict__ albw,
                        const float* __restrict__ W,     // [64,128] row-major
                        const float* __restrict__ b,
                        const int* __restrict__ aid,
                        const int* __restrict__ bid)
{
    // zero g_pack / g_desc (grid has 4.8M threads >> NN)
    int gtid = blockIdx.x * blockDim.x + threadIdx.x;
    if (gtid < NN) g_pack[gtid] = 0ULL;
    if (gtid < NB) g_desc[gtid] = 0ULL;

    int warp = threadIdx.x >> 5;
    int lane = threadIdx.x & 31;

    if (blockIdx.x < ITEM_BLOCKS) {
        __shared__ float Wsh[128 * 64];     // Wsh[k*64 + 2*lane..] = W[.,k]
        __shared__ float fsh[8][128];
        for (int idx = threadIdx.x; idx < 128 * 64; idx += blockDim.x) {
            int d = idx & 63, k = idx >> 6;
            Wsh[idx] = W[d * 128 + k];
        }
        __syncthreads();

        int item = blockIdx.x * 8 + warp;
        if (item >= II) return;
        int a = aid[item];
        int bb = bid[item];
        float2 au = ((const float2*)(audio + (size_t)item * DD))[lane];
        float2 m0 = ((const float2*)(artw  + (size_t)a    * DD))[lane];
        float2 m1 = ((const float2*)(albw  + (size_t)bb   * DD))[lane];
        ((float2*)(fsh[warp]))[lane]      = au;
        ((float2*)(fsh[warp] + 64))[lane] = make_float2(m0.x + m1.x, m0.y + m1.y);
        __syncwarp();

        float a0 = 0.f, a1 = 0.f;
        #pragma unroll
        for (int k = 0; k < 128; k++) {
            float f = fsh[warp][k];
            float2 wv = ((const float2*)(Wsh + k * 64))[lane];  // dims 2l, 2l+1
            a0 = fmaf(f, wv.x, a0);
            a1 = fmaf(f, wv.y, a1);
        }
        float2 bv = ((const float2*)b)[lane];
        a0 += bv.x;
        a1 += bv.y;
        float ss = a0 * a0 + a1 * a1;
        #pragma unroll
        for (int o = 16; o; o >>= 1) ss += __shfl_xor_sync(0xffffffffu, ss, o);
        float inv = 1.0f / fmaxf(sqrtf(ss), 1e-12f);
        g_x0[((size_t)(UU + item)) * 32 + lane] =
            __float22half2_rn(make_float2(a0 * inv, a1 * inv));
    } else {
        int user = (blockIdx.x - ITEM_BLOCKS) * 8 + warp;
        if (user >= UU) return;
        float2 v = ((const float2*)(uw + (size_t)user * DD))[lane];
        float ss = v.x * v.x + v.y * v.y;
        #pragma unroll
        for (int o = 16; o; o >>= 1) ss += __shfl_xor_sync(0xffffffffu, ss, o);
        float inv = 1.0f / fmaxf(sqrtf(ss), 1e-12f);
        g_x0[(size_t)user * 32 + lane] =
            __float22half2_rn(make_float2(v.x * inv, v.y * inv));
    }
}

// ---------------------------------------------------------------------------
// one 64-bit atomic per endpoint: count in bits [44..), weighted degree
// (2^20 fixed point) in low bits.
__global__ void k_edge_stats(const float* __restrict__ ew,
                             const int* __restrict__ ui,
                             const int* __restrict__ ii)
{
    int e = blockIdx.x * blockDim.x + threadIdx.x;
    if (e >= EE) return;
    float w = fmaxf(ew[e], 1e-6f);
    unsigned long long val = (1ULL << 44) |
        (unsigned long long)(w * FIXS + 0.5f);
    int u = ui[e];
    int v = ii[e] + UU;
    atomicAdd(&g_pack[u], val);
    atomicAdd(&g_pack[v], val);
}

// ---------------------------------------------------------------------------
// single-pass decoupled-lookback scan (warp-shuffle version, 2 barriers).
// Also computes dinv, inits g_pos, writes pad edges.  147 blocks co-resident.
__global__ void k_scan1()
{
    __shared__ int wsum[32];
    __shared__ int sbase;
    int t = threadIdx.x;
    int b = blockIdx.x;
    int i = b * 1024 + t;
    int lane = t & 31;
    int wid  = t >> 5;

    int cnt = 0, v = 0;
    if (i < NN) {
        cnt = (int)(g_pack[i] >> 44);
        v = (cnt + 3) & ~3;                          // pad bucket to multiple of 4
    }

    // warp inclusive scan
    int x = v;
    #pragma unroll
    for (int o = 1; o < 32; o <<= 1) {
        int y = __shfl_up_sync(0xffffffffu, x, o);
        if (lane >= o) x += y;
    }
    if (lane == 31) wsum[wid] = x;
    __syncthreads();
    if (wid == 0) {
        int s = wsum[lane];
        #pragma unroll
        for (int o = 1; o < 32; o <<= 1) {
            int y = __shfl_up_sync(0xffffffffu, s, o);
            if (lane >= o) s += y;
        }
        wsum[lane] = s;
    }
    __syncthreads();
    int incl = x + (wid > 0 ? wsum[wid - 1] : 0);
    int agg  = wsum[31];

    if (t == 0) {
        if (b == 0) {
            atomicExch(&g_desc[0], (2ULL << 32) | (unsigned)agg);
            sbase = 0;
        } else {
            atomicExch(&g_desc[b], (1ULL << 32) | (unsigned)agg);
            int base = 0;
            for (int p = b - 1; p >= 0; ) {
                unsigned long long d2;
                do { d2 = atomicAdd(&g_desc[p], 0ULL); } while ((d2 >> 32) == 0);
                base += (int)(unsigned)d2;
                if ((d2 >> 32) == 2ULL) break;
                p--;
            }
            atomicExch(&g_desc[b], (2ULL << 32) | (unsigned)(base + agg));
            sbase = base;
        }
    }
    __syncthreads();
    int base = sbase;

    if (i < NN) {
        int o = base + incl - v;                     // exclusive prefix
        g_off[i] = o;
        g_pos[i] = o;
        unsigned long long p = g_pack[i];
        float deg = 1.0f + (float)(p & MASK44) * (1.0f / FIXS);  // +1 self loop
        g_dinv[i] = rsqrtf(deg);
        int pcnt = (cnt + 3) & ~3;
        for (int j = cnt; j < pcnt; j++)
            g_edge[o + j] = make_int2(i, 0);         // src=self (L1-hot), coef=0
        if (i == NN - 1) g_off[NN] = o + pcnt;
    }
}

// ---------------------------------------------------------------------------
// fill CSR: each undirected edge contributes both directions with coef c
__global__ void k_fill(const float* __restrict__ ew,
                       const int* __restrict__ ui,
                       const int* __restrict__ ii)
{
    int e = blockIdx.x * blockDim.x + threadIdx.x;
    if (e >= EE) return;
    float w = fmaxf(ew[e], 1e-6f);
    int u = ui[e];
    int v = ii[e] + UU;
    float c = g_dinv[u] * w * g_dinv[v];
    int cb = __float_as_int(c);
    int p0 = atomicAdd(&g_pos[v], 1);
    g_edge[p0] = make_int2(u, cb);
    int p1 = atomicAdd(&g_pos[u], 1);
    g_edge[p1] = make_int2(v, cb);
}

// ---------------------------------------------------------------------------
// one LGConv layer: warp per dest node; branch-free buckets padded to 4.
// 2 broadcast int4 edge loads + 4 independent half2 row gathers + FMAs.
// layer 2 fuses the finalize: out = l2norm((x0+x1+x2+x3)/4); x3 never stored.
__global__ void __launch_bounds__(256) k_prop(int layer, float* __restrict__ out)
{
    const __half2* __restrict__ x  = (layer == 0) ? g_x0 : (layer == 1) ? g_x1 : g_x2;
    __half2*       __restrict__ xn = (layer == 0) ? g_x1 : g_x2;

    int warp = (blockIdx.x * blockDim.x + threadIdx.x) >> 5;
    int lane = threadIdx.x & 31;
    if (warp >= NN) return;
    int dest = warp;

    float2 v = __half22float2(x[(size_t)dest * 32 + lane]);
    float di = g_dinv[dest];
    float cs = di * di;                       // self-loop coefficient
    float rx = cs * v.x, ry = cs * v.y;

    int e   = g_off[dest];
    int end = g_off[dest + 1];                // always a multiple of 4 edges
    for (; e < end; e += 4) {
        int4 ea = __ldg((const int4*)(g_edge + e));       // edges e, e+1
        int4 eb = __ldg((const int4*)(g_edge + e + 2));   // edges e+2, e+3
        float2 v0 = __half22float2(__ldg(&x[(size_t)ea.x * 32 + lane]));
        float2 v1 = __half22float2(__ldg(&x[(size_t)ea.z * 32 + lane]));
        float2 v2 = __half22float2(__ldg(&x[(size_t)eb.x * 32 + lane]));
        float2 v3 = __half22float2(__ldg(&x[(size_t)eb.z * 32 + lane]));
        float c0 = __int_as_float(ea.y), c1 = __int_as_float(ea.w);
        float c2 = __int_as_float(eb.y), c3 = __int_as_float(eb.w);
        rx = fmaf(c0, v0.x, rx); ry = fmaf(c0, v0.y, ry);
        rx = fmaf(c1, v1.x, rx); ry = fmaf(c1, v1.y, ry);
        rx = fmaf(c2, v2.x, rx); ry = fmaf(c2, v2.y, ry);
        rx = fmaf(c3, v3.x, rx); ry = fmaf(c3, v3.y, ry);
    }

    if (layer < 2) {
        xn[(size_t)dest * 32 + lane] = __float22half2_rn(make_float2(rx, ry));
    } else {
        // fused finalize: rx,ry = x3 (fp32, pre-round)
        size_t idx = (size_t)dest * 32 + lane;
        float2 a0 = __half22float2(g_x0[idx]);
        float2 a1 = __half22float2(g_x1[idx]);
        float2 a2 = __half22float2(g_x2[idx]);
        float sx = (a0.x + a1.x + a2.x + rx) * 0.25f;
        float sy = (a0.y + a1.y + a2.y + ry) * 0.25f;
        float ss = sx * sx + sy * sy;
        #pragma unroll
        for (int o = 16; o; o >>= 1) ss += __shfl_xor_sync(0xffffffffu, ss, o);
        float inv = 1.0f / fmaxf(sqrtf(ss), 1e-12f);
        ((float2*)(out + (size_t)dest * DD))[lane] = make_float2(sx * inv, sy * inv);
    }
}

// ---------------------------------------------------------------------------
extern "C" void kernel_launch(void* const* d_in, const int* in_sizes, int n_in,
                              void* d_out, int out_size)
{
    const float* user_w     = (const float*)d_in[0];
    const float* item_audio = (const float*)d_in[1];
    const float* artist_w   = (const float*)d_in[2];
    const float* album_w    = (const float*)d_in[3];
    const float* proj_W     = (const float*)d_in[4];
    const float* proj_b     = (const float*)d_in[5];
    const float* edge_w     = (const float*)d_in[6];
    const int*   u_idx      = (const int*)  d_in[7];
    const int*   i_idx      = (const int*)  d_in[8];
    const int*   artist_ids = (const int*)  d_in[9];
    const int*   album_ids  = (const int*)  d_in[10];
    float* out = (float*)d_out;

    // maximize L1 for the gather-heavy prop kernel (uses no shared memory)
    cudaFuncSetAttribute((const void*)k_prop,
                         cudaFuncAttributePreferredSharedMemoryCarveout, 0);

    const int T = 256;
    int nBlocksE = (EE + T - 1) / T;
    int nWarpBlocksN = (NN * 32 + T - 1) / T;   // warp-per-node kernels

    // 1: fused embeds + scratch zeroing
    k_embed<<<EMBED_BLOCKS, T>>>(user_w, item_audio, artist_w, album_w,
                                 proj_W, proj_b, artist_ids, album_ids);
    // 2: degree/count accumulation
    k_edge_stats<<<nBlocksE, T>>>(edge_w, u_idx, i_idx);
    // 3: single-pass scan (+dinv, pos, pads)
    k_scan1<<<NB, 1024>>>();
    // 4: CSR fill  (<- profiled launch)
    k_fill<<<nBlocksE, T>>>(edge_w, u_idx, i_idx);
    // 5-7: LGConv layers; layer 2 fuses the finalize
    k_prop<<<nWarpBlocksN, T>>>(0, nullptr);   // x0 -> x1
    k_prop<<<nWarpBlocksN, T>>>(1, nullptr);   // x1 -> x2
    k_prop<<<nWarpBlocksN, T>>>(2, out);       // x2 -> (x3) -> out
}

// round 16
// speedup vs baseline: 1.5242x; 1.5242x over previous
#include <cuda_runtime.h>
#include <cuda_fp16.h>
#include <math.h>

#define UU 100000
#define II 50000
#define DD 64
#define EE 2000000
#define NN 150000   // UU + II
#define NB 147      // ceil(NN / 1024) scan blocks
#define FIXS 1048576.0f              // 2^20 fixed-point scale for degree
#define MASK44 ((1ULL << 44) - 1ULL)
#define ITEM_BLOCKS 6250             // II / 8
#define USER_BLOCKS 12500            // UU / 8
#define EMBED_BLOCKS (ITEM_BLOCKS + USER_BLOCKS)

// ---- device scratch (static; no allocation anywhere) ----
__device__ __half2 g_x0[NN * 32];    // layer outputs, fp16: row = 32 half2 = 128 B
__device__ __half2 g_x1[NN * 32];
__device__ __half2 g_x2[NN * 32];
__device__ int2    g_edge[2 * EE + 3 * NN + 8];  // padded (mult of 4) CSR payload
__device__ unsigned long long g_pack[NN];        // (cnt << 44) | deg_fixedpoint
__device__ unsigned long long g_desc[NB];        // lookback: (state<<32)|value
__device__ float g_dinv[NN];
__device__ int   g_off [NN + 1];
__device__ int   g_pos [NN];

// ---------------------------------------------------------------------------
// fused L0 embeddings + scratch zeroing.
// blocks [0, ITEM_BLOCKS): item path; [ITEM_BLOCKS, EMBED_BLOCKS): user path.
__global__ void k_embed(const float* __restrict__ uw,
                        const float* __restrict__ audio,
                        const float* __restrict__ artw,
                        const float* __restrict__ albw,
                        const float* __restrict__ W,     // [64,128] row-major
                        const float* __restrict__ b,
                        const int* __restrict__ aid,
                        const int* __restrict__ bid)
{
    // zero g_pack / g_desc (grid has 4.8M threads >> NN)
    int gtid = blockIdx.x * blockDim.x + threadIdx.x;
    if (gtid < NN) g_pack[gtid] = 0ULL;
    if (gtid < NB) g_desc[gtid] = 0ULL;

    int warp = threadIdx.x >> 5;
    int lane = threadIdx.x & 31;

    if (blockIdx.x < ITEM_BLOCKS) {
        __shared__ float Wsh[128 * 64];     // Wsh[k*64 + 2*lane..] = W[.,k]
        __shared__ float fsh[8][128];
        for (int idx = threadIdx.x; idx < 128 * 64; idx += blockDim.x) {
            int d = idx & 63, k = idx >> 6;
            Wsh[idx] = W[d * 128 + k];
        }
        __syncthreads();

        int item = blockIdx.x * 8 + warp;
        if (item >= II) return;
        int a = aid[item];
        int bb = bid[item];
        float2 au = ((const float2*)(audio + (size_t)item * DD))[lane];
        float2 m0 = ((const float2*)(artw  + (size_t)a    * DD))[lane];
        float2 m1 = ((const float2*)(albw  + (size_t)bb   * DD))[lane];
        ((float2*)(fsh[warp]))[lane]      = au;
        ((float2*)(fsh[warp] + 64))[lane] = make_float2(m0.x + m1.x, m0.y + m1.y);
        __syncwarp();

        float a0 = 0.f, a1 = 0.f;
        #pragma unroll
        for (int k = 0; k < 128; k++) {
            float f = fsh[warp][k];
            float2 wv = ((const float2*)(Wsh + k * 64))[lane];  // dims 2l, 2l+1
            a0 = fmaf(f, wv.x, a0);
            a1 = fmaf(f, wv.y, a1);
        }
        float2 bv = ((const float2*)b)[lane];
        a0 += bv.x;
        a1 += bv.y;
        float ss = a0 * a0 + a1 * a1;
        #pragma unroll
        for (int o = 16; o; o >>= 1) ss += __shfl_xor_sync(0xffffffffu, ss, o);
        float inv = 1.0f / fmaxf(sqrtf(ss), 1e-12f);
        g_x0[((size_t)(UU + item)) * 32 + lane] =
            __float22half2_rn(make_float2(a0 * inv, a1 * inv));
    } else {
        int user = (blockIdx.x - ITEM_BLOCKS) * 8 + warp;
        if (user >= UU) return;
        float2 v = ((const float2*)(uw + (size_t)user * DD))[lane];
        float ss = v.x * v.x + v.y * v.y;
        #pragma unroll
        for (int o = 16; o; o >>= 1) ss += __shfl_xor_sync(0xffffffffu, ss, o);
        float inv = 1.0f / fmaxf(sqrtf(ss), 1e-12f);
        g_x0[(size_t)user * 32 + lane] =
            __float22half2_rn(make_float2(v.x * inv, v.y * inv));
    }
}

// ---------------------------------------------------------------------------
// one 64-bit atomic per endpoint: count in bits [44..), weighted degree
// (2^20 fixed point) in low bits.
__global__ void k_edge_stats(const float* __restrict__ ew,
                             const int* __restrict__ ui,
                             const int* __restrict__ ii)
{
    int e = blockIdx.x * blockDim.x + threadIdx.x;
    if (e >= EE) return;
    float w = fmaxf(ew[e], 1e-6f);
    unsigned long long val = (1ULL << 44) |
        (unsigned long long)(w * FIXS + 0.5f);
    int u = ui[e];
    int v = ii[e] + UU;
    atomicAdd(&g_pack[u], val);
    atomicAdd(&g_pack[v], val);
}

// ---------------------------------------------------------------------------
// single-pass decoupled-lookback scan (warp-shuffle version, 2 barriers).
// Also computes dinv, inits g_pos, writes pad edges.  147 blocks co-resident.
__global__ void k_scan1()
{
    __shared__ int wsum[32];
    __shared__ int sbase;
    int t = threadIdx.x;
    int b = blockIdx.x;
    int i = b * 1024 + t;
    int lane = t & 31;
    int wid  = t >> 5;

    int cnt = 0, v = 0;
    if (i < NN) {
        cnt = (int)(g_pack[i] >> 44);
        v = (cnt + 3) & ~3;                          // pad bucket to multiple of 4
    }

    // warp inclusive scan
    int x = v;
    #pragma unroll
    for (int o = 1; o < 32; o <<= 1) {
        int y = __shfl_up_sync(0xffffffffu, x, o);
        if (lane >= o) x += y;
    }
    if (lane == 31) wsum[wid] = x;
    __syncthreads();
    if (wid == 0) {
        int s = wsum[lane];
        #pragma unroll
        for (int o = 1; o < 32; o <<= 1) {
            int y = __shfl_up_sync(0xffffffffu, s, o);
            if (lane >= o) s += y;
        }
        wsum[lane] = s;
    }
    __syncthreads();
    int incl = x + (wid > 0 ? wsum[wid - 1] : 0);
    int agg  = wsum[31];

    if (t == 0) {
        if (b == 0) {
            atomicExch(&g_desc[0], (2ULL << 32) | (unsigned)agg);
            sbase = 0;
        } else {
            atomicExch(&g_desc[b], (1ULL << 32) | (unsigned)agg);
            int base = 0;
            for (int p = b - 1; p >= 0; ) {
                unsigned long long d2;
                do { d2 = atomicAdd(&g_desc[p], 0ULL); } while ((d2 >> 32) == 0);
                base += (int)(unsigned)d2;
                if ((d2 >> 32) == 2ULL) break;
                p--;
            }
            atomicExch(&g_desc[b], (2ULL << 32) | (unsigned)(base + agg));
            sbase = base;
        }
    }
    __syncthreads();
    int base = sbase;

    if (i < NN) {
        int o = base + incl - v;                     // exclusive prefix
        g_off[i] = o;
        g_pos[i] = o;
        unsigned long long p = g_pack[i];
        float deg = 1.0f + (float)(p & MASK44) * (1.0f / FIXS);  // +1 self loop
        g_dinv[i] = rsqrtf(deg);
        int pcnt = (cnt + 3) & ~3;
        for (int j = cnt; j < pcnt; j++)
            g_edge[o + j] = make_int2(i, 0);         // src=self (L1-hot), coef=0
        if (i == NN - 1) g_off[NN] = o + pcnt;
    }
}

// ---------------------------------------------------------------------------
// fill CSR: each undirected edge contributes both directions with coef c
__global__ void k_fill(const float* __restrict__ ew,
                       const int* __restrict__ ui,
                       const int* __restrict__ ii)
{
    int e = blockIdx.x * blockDim.x + threadIdx.x;
    if (e >= EE) return;
    float w = fmaxf(ew[e], 1e-6f);
    int u = ui[e];
    int v = ii[e] + UU;
    float c = g_dinv[u] * w * g_dinv[v];
    int cb = __float_as_int(c);
    int p0 = atomicAdd(&g_pos[v], 1);
    g_edge[p0] = make_int2(u, cb);
    int p1 = atomicAdd(&g_pos[u], 1);
    g_edge[p1] = make_int2(v, cb);
}

// ---------------------------------------------------------------------------
// one LGConv layer: warp per dest node; branch-free buckets padded to 4.
// 2 broadcast int4 edge loads + 4 independent half2 row gathers + FMAs.
// layer 2 fuses the finalize: out = l2norm((x0+x1+x2+x3)/4); x3 never stored.
__global__ void __launch_bounds__(256) k_prop(int layer, float* __restrict__ out)
{
    const __half2* __restrict__ x  = (layer == 0) ? g_x0 : (layer == 1) ? g_x1 : g_x2;
    __half2*       __restrict__ xn = (layer == 0) ? g_x1 : g_x2;

    int warp = (blockIdx.x * blockDim.x + threadIdx.x) >> 5;
    int lane = threadIdx.x & 31;
    if (warp >= NN) return;
    int dest = warp;

    float2 v = __half22float2(x[(size_t)dest * 32 + lane]);
    float di = g_dinv[dest];
    float cs = di * di;                       // self-loop coefficient
    float rx = cs * v.x, ry = cs * v.y;

    int e   = g_off[dest];
    int end = g_off[dest + 1];                // always a multiple of 4 edges
    for (; e < end; e += 4) {
        int4 ea = __ldg((const int4*)(g_edge + e));       // edges e, e+1
        int4 eb = __ldg((const int4*)(g_edge + e + 2));   // edges e+2, e+3
        float2 v0 = __half22float2(__ldg(&x[(size_t)ea.x * 32 + lane]));
        float2 v1 = __half22float2(__ldg(&x[(size_t)ea.z * 32 + lane]));
        float2 v2 = __half22float2(__ldg(&x[(size_t)eb.x * 32 + lane]));
        float2 v3 = __half22float2(__ldg(&x[(size_t)eb.z * 32 + lane]));
        float c0 = __int_as_float(ea.y), c1 = __int_as_float(ea.w);
        float c2 = __int_as_float(eb.y), c3 = __int_as_float(eb.w);
        rx = fmaf(c0, v0.x, rx); ry = fmaf(c0, v0.y, ry);
        rx = fmaf(c1, v1.x, rx); ry = fmaf(c1, v1.y, ry);
        rx = fmaf(c2, v2.x, rx); ry = fmaf(c2, v2.y, ry);
        rx = fmaf(c3, v3.x, rx); ry = fmaf(c3, v3.y, ry);
    }

    if (layer < 2) {
        xn[(size_t)dest * 32 + lane] = __float22half2_rn(make_float2(rx, ry));
    } else {
        // fused finalize: rx,ry = x3 (fp32, pre-round)
        size_t idx = (size_t)dest * 32 + lane;
        float2 a0 = __half22float2(g_x0[idx]);
        float2 a1 = __half22float2(g_x1[idx]);
        float2 a2 = __half22float2(g_x2[idx]);
        float sx = (a0.x + a1.x + a2.x + rx) * 0.25f;
        float sy = (a0.y + a1.y + a2.y + ry) * 0.25f;
        float ss = sx * sx + sy * sy;
        #pragma unroll
        for (int o = 16; o; o >>= 1) ss += __shfl_xor_sync(0xffffffffu, ss, o);
        float inv = 1.0f / fmaxf(sqrtf(ss), 1e-12f);
        ((float2*)(out + (size_t)dest * DD))[lane] = make_float2(sx * inv, sy * inv);
    }
}

// ---------------------------------------------------------------------------
extern "C" void kernel_launch(void* const* d_in, const int* in_sizes, int n_in,
                              void* d_out, int out_size)
{
    const float* user_w     = (const float*)d_in[0];
    const float* item_audio = (const float*)d_in[1];
    const float* artist_w   = (const float*)d_in[2];
    const float* album_w    = (const float*)d_in[3];
    const float* proj_W     = (const float*)d_in[4];
    const float* proj_b     = (const float*)d_in[5];
    const float* edge_w     = (const float*)d_in[6];
    const int*   u_idx      = (const int*)  d_in[7];
    const int*   i_idx      = (const int*)  d_in[8];
    const int*   artist_ids = (const int*)  d_in[9];
    const int*   album_ids  = (const int*)  d_in[10];
    float* out = (float*)d_out;

    const int T = 256;
    int nBlocksE = (EE + T - 1) / T;
    int nWarpBlocksN = (NN * 32 + T - 1) / T;   // warp-per-node kernels

    // 1: fused embeds + scratch zeroing
    k_embed<<<EMBED_BLOCKS, T>>>(user_w, item_audio, artist_w, album_w,
                                 proj_W, proj_b, artist_ids, album_ids);
    // 2: degree/count accumulation
    k_edge_stats<<<nBlocksE, T>>>(edge_w, u_idx, i_idx);
    // 3: single-pass scan (+dinv, pos, pads)
    k_scan1<<<NB, 1024>>>();
    // 4: CSR fill  (<- profiled launch)
    k_fill<<<nBlocksE, T>>>(edge_w, u_idx, i_idx);
    // 5-7: LGConv layers; layer 2 fuses the finalize
    k_prop<<<nWarpBlocksN, T>>>(0, nullptr);   // x0 -> x1
    k_prop<<<nWarpBlocksN, T>>>(1, nullptr);   // x1 -> x2
    k_prop<<<nWarpBlocksN, T>>>(2, out);       // x2 -> (x3) -> out
}